// round 3
// baseline (speedup 1.0000x reference)
#include <cuda_runtime.h>
#include <math.h>

#define Bb 4
#define Tt 12
#define Nn 2048
#define Ff 64
#define Hh 4
#define Dd 16
#define Cc 64
#define BT (Bb*Tt)          // 48
#define Mm (BT*Nn)          // 98304 rows
#define CAP 128

// ---------------- scratch (device globals; no allocation allowed) -----------
__device__ float g_Wcat[Ff*256];                       // packed [64][256] weights
__device__ int   g_nbr[Bb*Nn*CAP];                     // neighbor lists
__device__ int   g_deg[Bb*Nn];
__device__ float g_Y[(size_t)Mm*256];                  // [m][0:64 Fz | 64:128 Fh | 128:192 XWz+b | 192:256 XWh+b]
__device__ float g_f1[2][BT*Hh*Nn];                    // [gate][bt*H+h][n]
__device__ float g_f2[2][BT*Hh*Nn];
__device__ float g_G[2][(size_t)Tt*Bb*Nn*Cc];          // pre-activation gate inputs [t][b][n][c]

// ---------------- K0: pack Wcat = [Wg_z | Wg_h | W_z | W_h] -----------------
__global__ void k0_wcat(const float* __restrict__ Wg_z, const float* __restrict__ Wg_h,
                        const float* __restrict__ W_z,  const float* __restrict__ W_h) {
    int c = threadIdx.x;  // 0..255
    for (int f = 0; f < Ff; f++) {
        float v;
        if (c < 64)       v = Wg_z[(c >> 4) * Ff * Dd + f * Dd + (c & 15)];
        else if (c < 128) { int cc = c - 64; v = Wg_h[(cc >> 4) * Ff * Dd + f * Dd + (cc & 15)]; }
        else if (c < 192) v = W_z[f * Cc + (c - 128)];
        else              v = W_h[f * Cc + (c - 192)];
        g_Wcat[f * 256 + c] = v;
    }
}

// ---------------- K1: build neighbor lists (deterministic order) ------------
__global__ void __launch_bounds__(256) k1_adj(const float* __restrict__ bias) {
    __shared__ int cnt[256];
    __shared__ int off[256];
    int row = blockIdx.x;  // b*N + n
    const float* bp = bias + (size_t)row * Nn;
    int tid = threadIdx.x;
    int base = tid * 8;
    float4 v0 = *(const float4*)(bp + base);
    float4 v1 = *(const float4*)(bp + base + 4);
    float vals[8] = {v0.x, v0.y, v0.z, v0.w, v1.x, v1.y, v1.z, v1.w};
    int idxs[8];
    int local = 0;
#pragma unroll
    for (int i = 0; i < 8; i++)
        if (vals[i] > -1.0f) idxs[local++] = base + i;  // 0.0 = edge, -1e9 = masked
    cnt[tid] = local;
    __syncthreads();
    if (tid == 0) {
        int s = 0;
        for (int i = 0; i < 256; i++) { off[i] = s; s += cnt[i]; }
        g_deg[row] = (s < CAP) ? s : CAP;
    }
    __syncthreads();
    int o = off[tid];
    int* np = g_nbr + (size_t)row * CAP;
    for (int i = 0; i < local; i++) { int p = o + i; if (p < CAP) np[p] = idxs[i]; }
}

// ---------------- K2: X[M,64] @ Wcat[64,256] -> g_Y (+ bias on XW cols) -----
__global__ void __launch_bounds__(256) k2_gemm(const float* __restrict__ X,
                                               const float* __restrict__ Zb,
                                               const float* __restrict__ Hb) {
    __shared__ __align__(16) float Ws[16 * 256];
    __shared__ __align__(16) float Xs[16 * 68];   // transposed [k][row], padded
    int m0 = blockIdx.x * 64;
    int tid = threadIdx.x;
    int tc = tid & 31, tr = tid >> 5;
    float acc[8][8];
#pragma unroll
    for (int i = 0; i < 8; i++)
#pragma unroll
        for (int j = 0; j < 8; j++) acc[i][j] = 0.f;

    for (int kc = 0; kc < 4; kc++) {
        int k0 = kc * 16;
        // stage W chunk (16x256 = full rows of Wcat, contiguous)
        const float4* src = (const float4*)(g_Wcat + k0 * 256);
        float4* dst = (float4*)Ws;
        for (int q = tid; q < 1024; q += 256) dst[q] = src[q];
        // stage X chunk transposed
        {
            int row = tid >> 2, v = tid & 3;
            float4 xv = *(const float4*)(X + (size_t)(m0 + row) * Ff + k0 + v * 4);
            Xs[(v * 4 + 0) * 68 + row] = xv.x;
            Xs[(v * 4 + 1) * 68 + row] = xv.y;
            Xs[(v * 4 + 2) * 68 + row] = xv.z;
            Xs[(v * 4 + 3) * 68 + row] = xv.w;
        }
        __syncthreads();
#pragma unroll
        for (int k = 0; k < 16; k++) {
            float4 w0 = *(const float4*)(Ws + k * 256 + tc * 4);
            float4 w1 = *(const float4*)(Ws + k * 256 + 128 + tc * 4);
            float4 x0 = *(const float4*)(Xs + k * 68 + tr * 8);
            float4 x1 = *(const float4*)(Xs + k * 68 + tr * 8 + 4);
            float xr[8] = {x0.x, x0.y, x0.z, x0.w, x1.x, x1.y, x1.z, x1.w};
            float wc[8] = {w0.x, w0.y, w0.z, w0.w, w1.x, w1.y, w1.z, w1.w};
#pragma unroll
            for (int i = 0; i < 8; i++)
#pragma unroll
                for (int j = 0; j < 8; j++) acc[i][j] += xr[i] * wc[j];
        }
        __syncthreads();
    }
    int colA = tc * 4, colB = 128 + tc * 4;
    float biasB[4];
#pragma unroll
    for (int j = 0; j < 4; j++) {
        int cb = colB + j;
        biasB[j] = (cb < 192) ? Zb[cb - 128] : Hb[cb - 192];
    }
#pragma unroll
    for (int i = 0; i < 8; i++) {
        size_t base = (size_t)(m0 + tr * 8 + i) * 256;
        float4 a = {acc[i][0], acc[i][1], acc[i][2], acc[i][3]};
        *(float4*)(g_Y + base + colA) = a;
        float4 bv = {acc[i][4] + biasB[0], acc[i][5] + biasB[1],
                     acc[i][6] + biasB[2], acc[i][7] + biasB[3]};
        *(float4*)(g_Y + base + colB) = bv;
    }
}

// ---------------- K2b: f1/f2 head dots for both gates -----------------------
__global__ void k2b_f(const float* __restrict__ a1z, const float* __restrict__ a2z,
                      const float* __restrict__ a1h, const float* __restrict__ a2h) {
    int idx = blockIdx.x * blockDim.x + threadIdx.x;  // [bt][h][n]
    if (idx >= BT * Hh * Nn) return;
    int n = idx % Nn;
    int h = (idx / Nn) & 3;
    int bt = idx / (Nn * Hh);
    size_t yb = ((size_t)(bt * Nn + n)) * 256 + h * 16;
    const float4* vz4 = (const float4*)(g_Y + yb);
    const float4* vh4 = (const float4*)(g_Y + yb + 64);
    const float4* A1z = (const float4*)(a1z + h * 16);
    const float4* A2z = (const float4*)(a2z + h * 16);
    const float4* A1h = (const float4*)(a1h + h * 16);
    const float4* A2h = (const float4*)(a2h + h * 16);
    float f1z = 0, f2z = 0, f1h = 0, f2h = 0;
#pragma unroll
    for (int q = 0; q < 4; q++) {
        float4 vz = vz4[q], vh = vh4[q];
        float4 a = A1z[q];
        f1z += vz.x * a.x + vz.y * a.y + vz.z * a.z + vz.w * a.w;
        a = A2z[q];
        f2z += vz.x * a.x + vz.y * a.y + vz.z * a.z + vz.w * a.w;
        a = A1h[q];
        f1h += vh.x * a.x + vh.y * a.y + vh.z * a.z + vh.w * a.w;
        a = A2h[q];
        f2h += vh.x * a.x + vh.y * a.y + vh.z * a.z + vh.w * a.w;
    }
    g_f1[0][idx] = f1z; g_f2[0][idx] = f2z;
    g_f1[1][idx] = f1h; g_f2[1][idx] = f2h;
}

// ---------------- K3: sparse online-softmax attention + ELU + fuse XW -------
__global__ void __launch_bounds__(256) k3_attn(const float* __restrict__ bgz,
                                               const float* __restrict__ bgh) {
    int tid = threadIdx.x;
    int c = tid & 63;                            // channel = h*16+d
    int sub = tid >> 6;                          // 4 row-tasks per block
    long task = (long)blockIdx.x * 4 + sub;      // < 2*BT*N
    int g = (int)(task / ((long)BT * Nn));
    int r = (int)(task % ((long)BT * Nn));
    int bt = r / Nn, n = r % Nn;
    int b = bt / Tt, t = bt % Tt;
    int h = c >> 4;

    const int* np = g_nbr + (size_t)(b * Nn + n) * CAP;
    int deg = g_deg[b * Nn + n];
    float f1v = g_f1[g][(bt * Hh + h) * Nn + n];
    const float* f2p = g_f2[g] + (size_t)(bt * Hh + h) * Nn;
    const float* yb = g_Y + (size_t)bt * Nn * 256 + g * 64 + c;

    float m = -1e30f, s = 0.f, acc = 0.f;
    for (int i = 0; i < deg; i++) {
        int j = np[i];
        float l = f1v + f2p[j];
        l = (l >= 0.f) ? l : 0.2f * l;           // leaky_relu, slope 0.2
        float feat = yb[(size_t)j * 256];
        if (l > m) {
            float sc = __expf(m - l);
            s = s * sc + 1.f;
            acc = acc * sc + feat;
            m = l;
        } else {
            float e = __expf(l - m);
            s += e;
            acc += e * feat;
        }
    }
    float val = acc / s + (g == 0 ? bgz : bgh)[c];
    val = (val > 0.f) ? val : expm1f(val);        // ELU
    float xw = g_Y[((size_t)(bt * Nn + n)) * 256 + 128 + g * 64 + c];
    g_G[g][(((size_t)t * Bb + b) * Nn + n) * Cc + c] = val + xw;
}

// ---------------- K4: sequential GRU scan + BatchNorm -----------------------
__global__ void k4_scan(const float* __restrict__ gamma, const float* __restrict__ beta,
                        const float* __restrict__ mean,  const float* __restrict__ var,
                        float* __restrict__ out) {
    int idx = blockIdx.x * blockDim.x + threadIdx.x;  // (b*N+n)*64 + c
    if (idx >= Bb * Nn * Cc) return;
    int c = idx & 63;
    const float* gz = g_G[0];
    const float* gh = g_G[1];
    float hst = 0.f;
#pragma unroll
    for (int t = 0; t < Tt; t++) {
        size_t o = (size_t)t * (Bb * Nn * Cc) + idx;
        float z = 1.f / (1.f + __expf(-(gz[o] + hst)));
        float tv = tanhf(gh[o] + hst);
        hst = z * hst + (1.f - z) * tv;
    }
    out[idx] = (hst - mean[c]) * rsqrtf(var[c] + 1e-3f) * gamma[c] + beta[c];
}

// ---------------- launch -----------------------------------------------------
extern "C" void kernel_launch(void* const* d_in, const int* in_sizes, int n_in,
                              void* d_out, int out_size) {
    const float* X        = (const float*)d_in[0];
    const float* bias_mat = (const float*)d_in[1];
    const float* W_z      = (const float*)d_in[2];
    const float* Z_bias   = (const float*)d_in[3];
    const float* W_h      = (const float*)d_in[4];
    const float* H_bias   = (const float*)d_in[5];
    const float* Wg_z     = (const float*)d_in[6];
    const float* a1_z     = (const float*)d_in[7];
    const float* a2_z     = (const float*)d_in[8];
    const float* bg_z     = (const float*)d_in[9];
    const float* Wg_h     = (const float*)d_in[10];
    const float* a1_h     = (const float*)d_in[11];
    const float* a2_h     = (const float*)d_in[12];
    const float* bg_h     = (const float*)d_in[13];
    const float* bn_gamma = (const float*)d_in[14];
    const float* bn_beta  = (const float*)d_in[15];
    const float* bn_mean  = (const float*)d_in[16];
    const float* bn_var   = (const float*)d_in[17];
    float* out = (float*)d_out;

    k0_wcat<<<1, 256>>>(Wg_z, Wg_h, W_z, W_h);
    k1_adj<<<Bb * Nn, 256>>>(bias_mat);
    k2_gemm<<<Mm / 64, 256>>>(X, Z_bias, H_bias);
    k2b_f<<<(BT * Hh * Nn + 255) / 256, 256>>>(a1_z, a2_z, a1_h, a2_h);
    k3_attn<<<2 * BT * Nn / 4, 256>>>(bg_z, bg_h);
    k4_scan<<<(Bb * Nn * Cc + 255) / 256, 256>>>(bn_gamma, bn_beta, bn_mean, bn_var, out);
}

// round 4
// speedup vs baseline: 1.1511x; 1.1511x over previous
#include <cuda_runtime.h>
#include <math.h>

#define Bb 4
#define Tt 12
#define Nn 2048
#define Ff 64
#define Hh 4
#define Dd 16
#define Cc 64
#define BT (Bb*Tt)          // 48
#define Mm (BT*Nn)          // 98304 rows
#define CAP 128

// ---------------- scratch (device globals; no allocation allowed) -----------
__device__ float g_Wcat[Ff*256];                       // packed [64][256] weights
__device__ int   g_nbr[Bb*Nn*CAP];                     // neighbor lists
__device__ int   g_deg[Bb*Nn];
__device__ float g_Y[(size_t)Mm*256];                  // [m][0:64 Fz | 64:128 Fh | 128:192 XWz+b | 192:256 XWh+b]
__device__ float g_f1[2][BT*Hh*Nn];                    // [gate][bt*H+h][n]
__device__ float g_f2[2][BT*Hh*Nn];
__device__ float g_G[2][(size_t)Tt*Bb*Nn*Cc];          // pre-activation gate inputs [t][b][n][c]

// ---------------- K0: pack Wcat = [Wg_z | Wg_h | W_z | W_h] -----------------
__global__ void k0_wcat(const float* __restrict__ Wg_z, const float* __restrict__ Wg_h,
                        const float* __restrict__ W_z,  const float* __restrict__ W_h) {
    int c = threadIdx.x;  // 0..255
    for (int f = 0; f < Ff; f++) {
        float v;
        if (c < 64)       v = Wg_z[(c >> 4) * Ff * Dd + f * Dd + (c & 15)];
        else if (c < 128) { int cc = c - 64; v = Wg_h[(cc >> 4) * Ff * Dd + f * Dd + (cc & 15)]; }
        else if (c < 192) v = W_z[f * Cc + (c - 128)];
        else              v = W_h[f * Cc + (c - 192)];
        g_Wcat[f * 256 + c] = v;
    }
}

// ---------------- K1: build neighbor lists (deterministic order) ------------
__global__ void __launch_bounds__(256) k1_adj(const float* __restrict__ bias) {
    __shared__ int cnt[256];
    __shared__ int off[256];
    int row = blockIdx.x;  // b*N + n
    const float* bp = bias + (size_t)row * Nn;
    int tid = threadIdx.x;
    int base = tid * 8;
    float4 v0 = *(const float4*)(bp + base);
    float4 v1 = *(const float4*)(bp + base + 4);
    float vals[8] = {v0.x, v0.y, v0.z, v0.w, v1.x, v1.y, v1.z, v1.w};
    int idxs[8];
    int local = 0;
#pragma unroll
    for (int i = 0; i < 8; i++)
        if (vals[i] > -1.0f) idxs[local++] = base + i;  // 0.0 = edge, -1e9 = masked
    cnt[tid] = local;
    __syncthreads();
    if (tid == 0) {
        int s = 0;
        for (int i = 0; i < 256; i++) { off[i] = s; s += cnt[i]; }
        g_deg[row] = (s < CAP) ? s : CAP;
    }
    __syncthreads();
    int o = off[tid];
    int* np = g_nbr + (size_t)row * CAP;
    for (int i = 0; i < local; i++) { int p = o + i; if (p < CAP) np[p] = idxs[i]; }
}

// ---------------- K2: X[M,64] @ Wcat[64,256] -> g_Y (+ bias on XW cols) -----
__global__ void __launch_bounds__(256) k2_gemm(const float* __restrict__ X,
                                               const float* __restrict__ Zb,
                                               const float* __restrict__ Hb) {
    __shared__ __align__(16) float Ws[16 * 256];
    __shared__ __align__(16) float Xs[16 * 68];   // transposed [k][row], padded
    int m0 = blockIdx.x * 64;
    int tid = threadIdx.x;
    int tc = tid & 31, tr = tid >> 5;
    float acc[8][8];
#pragma unroll
    for (int i = 0; i < 8; i++)
#pragma unroll
        for (int j = 0; j < 8; j++) acc[i][j] = 0.f;

    for (int kc = 0; kc < 4; kc++) {
        int k0 = kc * 16;
        const float4* src = (const float4*)(g_Wcat + k0 * 256);
        float4* dst = (float4*)Ws;
        for (int q = tid; q < 1024; q += 256) dst[q] = src[q];
        {
            int row = tid >> 2, v = tid & 3;
            float4 xv = *(const float4*)(X + (size_t)(m0 + row) * Ff + k0 + v * 4);
            Xs[(v * 4 + 0) * 68 + row] = xv.x;
            Xs[(v * 4 + 1) * 68 + row] = xv.y;
            Xs[(v * 4 + 2) * 68 + row] = xv.z;
            Xs[(v * 4 + 3) * 68 + row] = xv.w;
        }
        __syncthreads();
#pragma unroll
        for (int k = 0; k < 16; k++) {
            float4 w0 = *(const float4*)(Ws + k * 256 + tc * 4);
            float4 w1 = *(const float4*)(Ws + k * 256 + 128 + tc * 4);
            float4 x0 = *(const float4*)(Xs + k * 68 + tr * 8);
            float4 x1 = *(const float4*)(Xs + k * 68 + tr * 8 + 4);
            float xr[8] = {x0.x, x0.y, x0.z, x0.w, x1.x, x1.y, x1.z, x1.w};
            float wc[8] = {w0.x, w0.y, w0.z, w0.w, w1.x, w1.y, w1.z, w1.w};
#pragma unroll
            for (int i = 0; i < 8; i++)
#pragma unroll
                for (int j = 0; j < 8; j++) acc[i][j] += xr[i] * wc[j];
        }
        __syncthreads();
    }
    int colA = tc * 4, colB = 128 + tc * 4;
    float biasB[4];
#pragma unroll
    for (int j = 0; j < 4; j++) {
        int cb = colB + j;
        biasB[j] = (cb < 192) ? Zb[cb - 128] : Hb[cb - 192];
    }
#pragma unroll
    for (int i = 0; i < 8; i++) {
        size_t base = (size_t)(m0 + tr * 8 + i) * 256;
        float4 a = {acc[i][0], acc[i][1], acc[i][2], acc[i][3]};
        *(float4*)(g_Y + base + colA) = a;
        float4 bv = {acc[i][4] + biasB[0], acc[i][5] + biasB[1],
                     acc[i][6] + biasB[2], acc[i][7] + biasB[3]};
        *(float4*)(g_Y + base + colB) = bv;
    }
}

// ---------------- K2b: f1/f2 head dots, SMEM-staged + coalesced -------------
__global__ void __launch_bounds__(256) k2b_f(const float* __restrict__ a1z, const float* __restrict__ a2z,
                                             const float* __restrict__ a1h, const float* __restrict__ a2h) {
    __shared__ __align__(16) float sY[64][132];   // 64 rows x first 128 cols (padded)
    __shared__ float sA[4][Hh][16];               // a1z,a2z,a1h,a2h per head
    int m0 = blockIdx.x * 64;
    int tid = threadIdx.x;
    // stage a-vectors (256 values, one per thread)
    {
        int arr = tid >> 6, rem = tid & 63;
        int h = rem >> 4, q = rem & 15;
        const float* ap = (arr == 0) ? a1z : (arr == 1) ? a2z : (arr == 2) ? a1h : a2h;
        sA[arr][h][q] = ap[h * 16 + q];
    }
    // stage 64 rows x 128 cols, fully coalesced float4
    for (int v = tid; v < 2048; v += 256) {
        int row = v >> 5, col4 = v & 31;
        float4 x = *(const float4*)(g_Y + (size_t)(m0 + row) * 256 + col4 * 4);
        *(float4*)(&sY[row][col4 * 4]) = x;
    }
    __syncthreads();

    int r = tid >> 2, h = tid & 3;
    float f1zv = 0.f, f2zv = 0.f, f1hv = 0.f, f2hv = 0.f;
#pragma unroll
    for (int q = 0; q < 16; q++) {
        float vz = sY[r][h * 16 + q];
        float vh = sY[r][64 + h * 16 + q];
        f1zv += vz * sA[0][h][q];
        f2zv += vz * sA[1][h][q];
        f1hv += vh * sA[2][h][q];
        f2hv += vh * sA[3][h][q];
    }
    int m = m0 + r;
    int bt = m / Nn, n = m % Nn;             // 64 | 2048 so whole block same bt
    int idx = (bt * Hh + h) * Nn + n;
    g_f1[0][idx] = f1zv; g_f2[0][idx] = f2zv;
    g_f1[1][idx] = f1hv; g_f2[1][idx] = f2hv;
}

// ---------------- K3: phase-split sparse softmax attention ------------------
__global__ void __launch_bounds__(256) k3_attn(const float* __restrict__ bgz,
                                               const float* __restrict__ bgh) {
    __shared__ int   s_nbr[4][CAP];
    __shared__ float s_w[4][CAP][4];       // logits -> exp weights, [sub][i][h]
    __shared__ float s_sum[4][Hh];
    __shared__ int   s_deg[4];

    int tid = threadIdx.x;
    int sub = tid >> 6;                    // 4 row-tasks per block
    int c   = tid & 63;                    // channel = h*16 + d
    long task = (long)blockIdx.x * 4 + sub;
    int g = (int)(task / ((long)BT * Nn));
    int r = (int)(task % ((long)BT * Nn));
    int bt = r / Nn, n = r % Nn;
    int b = bt / Tt, t = bt % Tt;

    int deg = g_deg[b * Nn + n];
    if (c == 0) s_deg[sub] = deg;
    const int* np = g_nbr + (size_t)(b * Nn + n) * CAP;
    for (int i = c; i < deg; i += 64) s_nbr[sub][i] = np[i];
    __syncthreads();

    // phase 1: logits, parallel over (i,h) -> 16x fewer exp-side redundancy
    {
        int h = c & 3, i0 = c >> 2;
        float f1v = g_f1[g][(bt * Hh + h) * Nn + n];
        const float* f2p = g_f2[g] + (size_t)(bt * Hh + h) * Nn;
        for (int i = i0; i < deg; i += 16) {
            int j = s_nbr[sub][i];
            float l = f1v + __ldg(f2p + j);
            l = (l >= 0.f) ? l : 0.2f * l;             // leaky_relu slope 0.2
            s_w[sub][i][h] = l;
        }
    }
    __syncthreads();

    // phase 2: deterministic serial softmax normalization per (task,h)
    if (c < 4) {
        int h = c;
        int dg = s_deg[sub];
        float m = -1e30f;
        for (int i = 0; i < dg; i++) m = fmaxf(m, s_w[sub][i][h]);
        float s = 0.f;
        for (int i = 0; i < dg; i++) {
            float e = __expf(s_w[sub][i][h] - m);
            s_w[sub][i][h] = e;
            s += e;
        }
        s_sum[sub][h] = s;
    }
    __syncthreads();

    // phase 3: weighted gather, unrolled x4 for MLP
    int h = c >> 4;
    int dg = s_deg[sub];
    const float* yb = g_Y + (size_t)bt * Nn * 256 + g * 64 + c;
    float acc = 0.f;
    int i = 0;
    for (; i + 4 <= dg; i += 4) {
        int j0 = s_nbr[sub][i],     j1 = s_nbr[sub][i + 1];
        int j2 = s_nbr[sub][i + 2], j3 = s_nbr[sub][i + 3];
        float w0 = s_w[sub][i][h],     w1 = s_w[sub][i + 1][h];
        float w2 = s_w[sub][i + 2][h], w3 = s_w[sub][i + 3][h];
        float a0 = yb[(size_t)j0 * 256], a1 = yb[(size_t)j1 * 256];
        float a2 = yb[(size_t)j2 * 256], a3 = yb[(size_t)j3 * 256];
        acc += w0 * a0; acc += w1 * a1; acc += w2 * a2; acc += w3 * a3;
    }
    for (; i < dg; i++)
        acc += s_w[sub][i][h] * yb[(size_t)s_nbr[sub][i] * 256];

    float val = acc / s_sum[sub][h] + (g == 0 ? bgz : bgh)[c];
    val = (val > 0.f) ? val : expm1f(val);             // ELU
    float xw = g_Y[((size_t)(bt * Nn + n)) * 256 + 128 + g * 64 + c];
    g_G[g][(((size_t)t * Bb + b) * Nn + n) * Cc + c] = val + xw;
}

// ---------------- K4: sequential GRU scan + BatchNorm -----------------------
__global__ void k4_scan(const float* __restrict__ gamma, const float* __restrict__ beta,
                        const float* __restrict__ mean,  const float* __restrict__ var,
                        float* __restrict__ out) {
    int idx = blockIdx.x * blockDim.x + threadIdx.x;  // (b*N+n)*64 + c
    if (idx >= Bb * Nn * Cc) return;
    int c = idx & 63;
    const float* gz = g_G[0];
    const float* gh = g_G[1];
    float hst = 0.f;
#pragma unroll
    for (int t = 0; t < Tt; t++) {
        size_t o = (size_t)t * (Bb * Nn * Cc) + idx;
        float z = 1.f / (1.f + __expf(-(gz[o] + hst)));
        float tv = tanhf(gh[o] + hst);
        hst = z * hst + (1.f - z) * tv;
    }
    out[idx] = (hst - mean[c]) * rsqrtf(var[c] + 1e-3f) * gamma[c] + beta[c];
}

// ---------------- launch -----------------------------------------------------
extern "C" void kernel_launch(void* const* d_in, const int* in_sizes, int n_in,
                              void* d_out, int out_size) {
    const float* X        = (const float*)d_in[0];
    const float* bias_mat = (const float*)d_in[1];
    const float* W_z      = (const float*)d_in[2];
    const float* Z_bias   = (const float*)d_in[3];
    const float* W_h      = (const float*)d_in[4];
    const float* H_bias   = (const float*)d_in[5];
    const float* Wg_z     = (const float*)d_in[6];
    const float* a1_z     = (const float*)d_in[7];
    const float* a2_z     = (const float*)d_in[8];
    const float* bg_z     = (const float*)d_in[9];
    const float* Wg_h     = (const float*)d_in[10];
    const float* a1_h     = (const float*)d_in[11];
    const float* a2_h     = (const float*)d_in[12];
    const float* bg_h     = (const float*)d_in[13];
    const float* bn_gamma = (const float*)d_in[14];
    const float* bn_beta  = (const float*)d_in[15];
    const float* bn_mean  = (const float*)d_in[16];
    const float* bn_var   = (const float*)d_in[17];
    float* out = (float*)d_out;

    k0_wcat<<<1, 256>>>(Wg_z, Wg_h, W_z, W_h);
    k1_adj<<<Bb * Nn, 256>>>(bias_mat);
    k2_gemm<<<Mm / 64, 256>>>(X, Z_bias, H_bias);
    k2b_f<<<Mm / 64, 256>>>(a1_z, a2_z, a1_h, a2_h);
    k3_attn<<<2 * BT * Nn / 4, 256>>>(bg_z, bg_h);
    k4_scan<<<(Bb * Nn * Cc + 255) / 256, 256>>>(bn_gamma, bn_beta, bn_mean, bn_var, out);
}

// round 8
// speedup vs baseline: 1.2543x; 1.0896x over previous
#include <cuda_runtime.h>
#include <math.h>

#define Bb 4
#define Tt 12
#define Nn 2048
#define Ff 64
#define Hh 4
#define Dd 16
#define Cc 64
#define BT (Bb*Tt)          // 48
#define Mm (BT*Nn)          // 98304 rows
#define CAP 128

// ---------------- scratch (device globals; no allocation allowed) -----------
__device__ float g_Wcat[Ff*256];                       // packed [64][256] weights
__device__ int   g_nbr[Bb*Nn*CAP];                     // neighbor lists
__device__ int   g_deg[Bb*Nn];
__device__ float g_Y[(size_t)Mm*256];                  // [m][0:64 Fz | 64:128 Fh | 128:192 XWz+b | 192:256 XWh+b]
__device__ float g_f1[2][BT*Hh*Nn];                    // [gate][bt*H+h][n]
__device__ float g_f2[2][BT*Hh*Nn];
__device__ float g_G[2][(size_t)Tt*Bb*Nn*Cc];          // pre-activation gate inputs [t][b][n][c]

// ---------------- K0: pack Wcat = [Wg_z | Wg_h | W_z | W_h] -----------------
__global__ void k0_wcat(const float* __restrict__ Wg_z, const float* __restrict__ Wg_h,
                        const float* __restrict__ W_z,  const float* __restrict__ W_h) {
    int c = threadIdx.x;  // 0..255
    for (int f = 0; f < Ff; f++) {
        float v;
        if (c < 64)       v = Wg_z[(c >> 4) * Ff * Dd + f * Dd + (c & 15)];
        else if (c < 128) { int cc = c - 64; v = Wg_h[(cc >> 4) * Ff * Dd + f * Dd + (cc & 15)]; }
        else if (c < 192) v = W_z[f * Cc + (c - 128)];
        else              v = W_h[f * Cc + (c - 192)];
        g_Wcat[f * 256 + c] = v;
    }
}

// ---------------- K1: build neighbor lists (deterministic order) ------------
__global__ void __launch_bounds__(256) k1_adj(const float* __restrict__ bias) {
    __shared__ int cnt[256];
    __shared__ int off[256];
    int row = blockIdx.x;  // b*N + n
    const float* bp = bias + (size_t)row * Nn;
    int tid = threadIdx.x;
    int base = tid * 8;
    float4 v0 = *(const float4*)(bp + base);
    float4 v1 = *(const float4*)(bp + base + 4);
    float vals[8] = {v0.x, v0.y, v0.z, v0.w, v1.x, v1.y, v1.z, v1.w};
    int idxs[8];
    int local = 0;
#pragma unroll
    for (int i = 0; i < 8; i++)
        if (vals[i] > -1.0f) idxs[local++] = base + i;  // 0.0 = edge, -1e9 = masked
    cnt[tid] = local;
    __syncthreads();
    if (tid == 0) {
        int s = 0;
        for (int i = 0; i < 256; i++) { off[i] = s; s += cnt[i]; }
        g_deg[row] = (s < CAP) ? s : CAP;
    }
    __syncthreads();
    int o = off[tid];
    int* np = g_nbr + (size_t)row * CAP;
    for (int i = 0; i < local; i++) { int p = o + i; if (p < CAP) np[p] = idxs[i]; }
}

// ---- K2: X[M,64] @ Wcat[64,256] -> g_Y, fused bias + f1/f2 head dots -------
__global__ void __launch_bounds__(256) k2_gemm(const float* __restrict__ X,
                                               const float* __restrict__ Zb,
                                               const float* __restrict__ Hb,
                                               const float* __restrict__ a1z,
                                               const float* __restrict__ a2z,
                                               const float* __restrict__ a1h,
                                               const float* __restrict__ a2h) {
    __shared__ __align__(16) float Ws[16 * 256];
    __shared__ __align__(16) float Xs[16 * 68];   // transposed [k][row], padded
    int m0 = blockIdx.x * 64;
    int tid = threadIdx.x;
    int tc = tid & 31, tr = tid >> 5;             // warp == tr, lane == tc
    float acc[8][8];
#pragma unroll
    for (int i = 0; i < 8; i++)
#pragma unroll
        for (int j = 0; j < 8; j++) acc[i][j] = 0.f;

    for (int kc = 0; kc < 4; kc++) {
        int k0 = kc * 16;
        const float4* src = (const float4*)(g_Wcat + k0 * 256);
        float4* dst = (float4*)Ws;
        for (int q = tid; q < 1024; q += 256) dst[q] = src[q];
        {
            int row = tid >> 2, v = tid & 3;
            float4 xv = *(const float4*)(X + (size_t)(m0 + row) * Ff + k0 + v * 4);
            Xs[(v * 4 + 0) * 68 + row] = xv.x;
            Xs[(v * 4 + 1) * 68 + row] = xv.y;
            Xs[(v * 4 + 2) * 68 + row] = xv.z;
            Xs[(v * 4 + 3) * 68 + row] = xv.w;
        }
        __syncthreads();
#pragma unroll
        for (int k = 0; k < 16; k++) {
            float4 w0 = *(const float4*)(Ws + k * 256 + tc * 4);
            float4 w1 = *(const float4*)(Ws + k * 256 + 128 + tc * 4);
            float4 x0 = *(const float4*)(Xs + k * 68 + tr * 8);
            float4 x1 = *(const float4*)(Xs + k * 68 + tr * 8 + 4);
            float xr[8] = {x0.x, x0.y, x0.z, x0.w, x1.x, x1.y, x1.z, x1.w};
            float wc[8] = {w0.x, w0.y, w0.z, w0.w, w1.x, w1.y, w1.z, w1.w};
#pragma unroll
            for (int i = 0; i < 8; i++)
#pragma unroll
                for (int j = 0; j < 8; j++) acc[i][j] += xr[i] * wc[j];
        }
        __syncthreads();
    }
    int colA = tc * 4, colB = 128 + tc * 4;
    float biasB[4];
#pragma unroll
    for (int j = 0; j < 4; j++) {
        int cb = colB + j;
        biasB[j] = (cb < 192) ? Zb[cb - 128] : Hb[cb - 192];
    }
    // store Y
#pragma unroll
    for (int i = 0; i < 8; i++) {
        size_t base = (size_t)(m0 + tr * 8 + i) * 256;
        float4 a = {acc[i][0], acc[i][1], acc[i][2], acc[i][3]};
        *(float4*)(g_Y + base + colA) = a;
        float4 bv = {acc[i][4] + biasB[0], acc[i][5] + biasB[1],
                     acc[i][6] + biasB[2], acc[i][7] + biasB[3]};
        *(float4*)(g_Y + base + colB) = bv;
    }
    // fused f1/f2: lanes 0-15 hold z-feature cols (0..63), lanes 16-31 h-feature cols
    bool isZ = (tc < 16);
    int hcol = isZ ? colA : colA - 64;            // 0..63 flat [H][16] index
    const float* a1p = isZ ? a1z : a1h;
    const float* a2p = isZ ? a2z : a2h;
    float A1[4], A2[4];
#pragma unroll
    for (int j = 0; j < 4; j++) { A1[j] = a1p[hcol + j]; A2[j] = a2p[hcol + j]; }
    int h = (tc >> 2) & 3;
    int gate = isZ ? 0 : 1;
#pragma unroll
    for (int i = 0; i < 8; i++) {
        float p1 = acc[i][0] * A1[0] + acc[i][1] * A1[1] + acc[i][2] * A1[2] + acc[i][3] * A1[3];
        float p2 = acc[i][0] * A2[0] + acc[i][1] * A2[1] + acc[i][2] * A2[2] + acc[i][3] * A2[3];
        p1 += __shfl_xor_sync(0xffffffffu, p1, 1);
        p1 += __shfl_xor_sync(0xffffffffu, p1, 2);
        p2 += __shfl_xor_sync(0xffffffffu, p2, 1);
        p2 += __shfl_xor_sync(0xffffffffu, p2, 2);
        if ((tc & 3) == 0) {
            int m = m0 + tr * 8 + i;
            int bt = m >> 11, n = m & (Nn - 1);
            int idx = (bt * Hh + h) * Nn + n;
            g_f1[gate][idx] = p1;
            g_f2[gate][idx] = p2;
        }
    }
}

// ---------------- K3: both-gate sparse softmax attention --------------------
__global__ void __launch_bounds__(256) k3_attn(const float* __restrict__ bgz,
                                               const float* __restrict__ bgh) {
    __shared__ int   s_nbr[2][CAP];
    __shared__ float s_w[2][CAP][9];       // [task][i][g*4+h], pad->9 (conflict-free)
    __shared__ float s_sum[2][8];
    __shared__ int   s_deg[2];

    int tid = threadIdx.x;
    int sub = tid >> 7;                    // 2 tasks per block
    int lt  = tid & 127;
    int task = blockIdx.x * 2 + sub;       // (bt, n)
    int bt = task >> 11, n = task & (Nn - 1);
    int b = bt / Tt, t = bt - b * Tt;

    int deg = g_deg[b * Nn + n];
    if (lt == 0) s_deg[sub] = deg;
    const int* np = g_nbr + (size_t)(b * Nn + n) * CAP;
    if (lt < deg) s_nbr[sub][lt] = np[lt];             // deg <= CAP = 128
    __syncthreads();

    // phase B: logits both gates; 128 threads = 16 i-slots x 8 (g,h)
    {
        int gh = lt & 7;                   // g*4 + h
        int g = gh >> 2, h = gh & 3;
        int i0 = lt >> 3;                  // 0..15
        float f1v = g_f1[g][(bt * Hh + h) * Nn + n];
        const float* f2p = g_f2[g] + (size_t)(bt * Hh + h) * Nn;
        for (int i = i0; i < deg; i += 16) {
            int j = s_nbr[sub][i];
            float l = f1v + __ldg(f2p + j);
            l = (l >= 0.f) ? l : 0.2f * l;             // leaky_relu slope 0.2
            s_w[sub][i][gh] = l;
        }
    }
    __syncthreads();

    // phase C: softmax per (g,h); 8 half-warp groups x 16 lanes, shuffle reduce
    {
        int lane16 = lt & 15;
        int gh = lt >> 4;                  // 0..7, aligned to half-warps
        float m = -1e30f;
        for (int i = lane16; i < deg; i += 16) m = fmaxf(m, s_w[sub][i][gh]);
#pragma unroll
        for (int o = 8; o; o >>= 1) m = fmaxf(m, __shfl_xor_sync(0xffffffffu, m, o, 16));
        float s = 0.f;
        for (int i = lane16; i < deg; i += 16) {
            float e = __expf(s_w[sub][i][gh] - m);
            s_w[sub][i][gh] = e;
            s += e;
        }
#pragma unroll
        for (int o = 8; o; o >>= 1) s += __shfl_xor_sync(0xffffffffu, s, o, 16);
        if (lane16 == 0) s_sum[sub][gh] = s;
    }
    __syncthreads();

    // phase D: weighted gather, thread = (g, c); unrolled x4 for MLP
    int g = lt >> 6, c = lt & 63, h = c >> 4;
    int gh = g * 4 + h;
    const float* yb = g_Y + (size_t)bt * Nn * 256 + g * 64 + c;
    float acc = 0.f;
    int i = 0;
    for (; i + 4 <= deg; i += 4) {
        int j0 = s_nbr[sub][i],     j1 = s_nbr[sub][i + 1];
        int j2 = s_nbr[sub][i + 2], j3 = s_nbr[sub][i + 3];
        float w0 = s_w[sub][i][gh],     w1 = s_w[sub][i + 1][gh];
        float w2 = s_w[sub][i + 2][gh], w3 = s_w[sub][i + 3][gh];
        float a0 = yb[(size_t)j0 * 256], a1 = yb[(size_t)j1 * 256];
        float a2 = yb[(size_t)j2 * 256], a3 = yb[(size_t)j3 * 256];
        acc += w0 * a0; acc += w1 * a1; acc += w2 * a2; acc += w3 * a3;
    }
    for (; i < deg; i++)
        acc += s_w[sub][i][gh] * yb[(size_t)s_nbr[sub][i] * 256];

    float val = acc / s_sum[sub][gh] + (g == 0 ? bgz : bgh)[c];
    val = (val > 0.f) ? val : expm1f(val);             // ELU
    float xw = g_Y[((size_t)(bt * Nn + n)) * 256 + 128 + g * 64 + c];
    g_G[g][(((size_t)t * Bb + b) * Nn + n) * Cc + c] = val + xw;
}

// ---------------- K4: sequential GRU scan + BatchNorm -----------------------
__global__ void k4_scan(const float* __restrict__ gamma, const float* __restrict__ beta,
                        const float* __restrict__ mean,  const float* __restrict__ var,
                        float* __restrict__ out) {
    int idx = blockIdx.x * blockDim.x + threadIdx.x;  // (b*N+n)*64 + c
    if (idx >= Bb * Nn * Cc) return;
    int c = idx & 63;
    const float* gz = g_G[0];
    const float* gh = g_G[1];
    float hst = 0.f;
#pragma unroll
    for (int t = 0; t < Tt; t++) {
        size_t o = (size_t)t * (Bb * Nn * Cc) + idx;
        float z = 1.f / (1.f + __expf(-(gz[o] + hst)));
        float tv = tanhf(gh[o] + hst);
        hst = z * hst + (1.f - z) * tv;
    }
    out[idx] = (hst - mean[c]) * rsqrtf(var[c] + 1e-3f) * gamma[c] + beta[c];
}

// ---------------- launch -----------------------------------------------------
extern "C" void kernel_launch(void* const* d_in, const int* in_sizes, int n_in,
                              void* d_out, int out_size) {
    const float* X        = (const float*)d_in[0];
    const float* bias_mat = (const float*)d_in[1];
    const float* W_z      = (const float*)d_in[2];
    const float* Z_bias   = (const float*)d_in[3];
    const float* W_h      = (const float*)d_in[4];
    const float* H_bias   = (const float*)d_in[5];
    const float* Wg_z     = (const float*)d_in[6];
    const float* a1_z     = (const float*)d_in[7];
    const float* a2_z     = (const float*)d_in[8];
    const float* bg_z     = (const float*)d_in[9];
    const float* Wg_h     = (const float*)d_in[10];
    const float* a1_h     = (const float*)d_in[11];
    const float* a2_h     = (const float*)d_in[12];
    const float* bg_h     = (const float*)d_in[13];
    const float* bn_gamma = (const float*)d_in[14];
    const float* bn_beta  = (const float*)d_in[15];
    const float* bn_mean  = (const float*)d_in[16];
    const float* bn_var   = (const float*)d_in[17];
    float* out = (float*)d_out;

    k0_wcat<<<1, 256>>>(Wg_z, Wg_h, W_z, W_h);
    k1_adj<<<Bb * Nn, 256>>>(bias_mat);
    k2_gemm<<<Mm / 64, 256>>>(X, Z_bias, H_bias, a1_z, a2_z, a1_h, a2_h);
    k3_attn<<<BT * Nn / 2, 256>>>(bg_z, bg_h);
    k4_scan<<<(Bb * Nn * Cc + 255) / 256, 256>>>(bn_gamma, bn_beta, bn_mean, bn_var, out);
}